// round 2
// baseline (speedup 1.0000x reference)
#include <cuda_runtime.h>
#include <cuda_bf16.h>
#include <stdint.h>

#define GRID_N 256

// Exact searchsorted(side='left') on a sorted axis, seeded analytically
// (axes are linspace(0,1,256)), corrected against the true values.
__device__ __forceinline__ void axis_terms(const float* __restrict__ p, float v,
                                           int& lo, int& hi,
                                           float& dl, float& dr, float& ov) {
    int g = (int)(v * 255.0f) + 1;
    g = min(max(g, 0), GRID_N - 1);
    while (g > 0 && p[g - 1] >= v) g--;
    while (g < GRID_N - 1 && p[g] < v) g++;
    hi = g;
    lo = max(g - 1, 0);
    dl = fmaxf(v - p[lo], 0.0f);
    dr = fmaxf(p[hi] - v, 0.0f);
    if (dl == 0.0f && dr == 0.0f) { dl = 1.0f; dr = 1.0f; }
    ov = dl + dr;
}

__device__ __forceinline__ float pick4(float4 q, int t) {
    float r = q.x;
    r = (t == 1) ? q.y : r;
    r = (t == 2) ? q.z : r;
    r = (t == 3) ? q.w : r;
    return r;
}

__global__ __launch_bounds__(256)
void trilerp_kernel(const float* __restrict__ x,
                    const float* __restrict__ y,
                    const float* __restrict__ z,
                    const float* __restrict__ px,
                    const float* __restrict__ py,
                    const float* __restrict__ pz,
                    const float* __restrict__ values,
                    float* __restrict__ out,
                    int K) {
    __shared__ float spx[GRID_N], spy[GRID_N], spz[GRID_N];
    int t0 = threadIdx.x;
    if (t0 < GRID_N) {
        spx[t0] = px[t0];
        spy[t0] = py[t0];
        spz[t0] = pz[t0];
    }
    __syncthreads();

    int i = blockIdx.x * blockDim.x + threadIdx.x;
    if (i >= K) return;

    float vx = x[i], vy = y[i], vz = z[i];

    int xlo, xhi, ylo, yhi, zlo, zhi;
    float dxl, dxr, ovx, dyl, dyr, ovy, dzl, dzr, ovz;
    axis_terms(spx, vx, xlo, xhi, dxl, dxr, ovx);
    axis_terms(spy, vy, ylo, yhi, dyl, dyr, ovy);
    axis_terms(spz, vz, zlo, zhi, dzl, dzr, ovz);

    // values[a][b][c]: c (z) contiguous
    const float* r00 = values + (((size_t)xlo << 8) + ylo) * GRID_N;
    const float* r01 = values + (((size_t)xlo << 8) + yhi) * GRID_N;
    const float* r10 = values + (((size_t)xhi << 8) + ylo) * GRID_N;
    const float* r11 = values + (((size_t)xhi << 8) + yhi) * GRID_N;

    // Aligned float4 covering z = [c, c+3]; contains zlo always, and zhi
    // unless t = zhi - c > 3 (only when zlo%4==3 and zhi==zlo+1).
    int c = zlo & ~3;
    int s = zlo - c;        // 0..3
    int t = zhi - c;        // s or s+1 (or s when zhi==zlo)

    const float4* q00p = (const float4*)(r00 + c);
    const float4* q01p = (const float4*)(r01 + c);
    const float4* q10p = (const float4*)(r10 + c);
    const float4* q11p = (const float4*)(r11 + c);

    float4 q00 = __ldg(q00p);
    float4 q01 = __ldg(q01p);
    float4 q10 = __ldg(q10p);
    float4 q11 = __ldg(q11p);

    bool need = (t > 3);
    float e00 = 0.f, e01 = 0.f, e10 = 0.f, e11 = 0.f;
    if (need) {
        e00 = __ldg(r00 + zhi);
        e01 = __ldg(r01 + zhi);
        e10 = __ldg(r10 + zhi);
        e11 = __ldg(r11 + zhi);
    }

    float v000 = pick4(q00, s);
    float v010 = pick4(q01, s);
    float v100 = pick4(q10, s);
    float v110 = pick4(q11, s);
    float v001 = need ? e00 : pick4(q00, t);
    float v011 = need ? e01 : pick4(q01, t);
    float v101 = need ? e10 : pick4(q10, t);
    float v111 = need ? e11 : pick4(q11, t);

    float num =
        v000 * (dxr * dyr * dzr) +
        v001 * (dxr * dyr * dzl) +
        v010 * (dxr * dyl * dzr) +
        v011 * (dxr * dyl * dzl) +
        v100 * (dxl * dyr * dzr) +
        v101 * (dxl * dyr * dzl) +
        v110 * (dxl * dyl * dzr) +
        v111 * (dxl * dyl * dzl);

    out[i] = num / (ovx * ovy * ovz);
}

extern "C" void kernel_launch(void* const* d_in, const int* in_sizes, int n_in,
                              void* d_out, int out_size) {
    const float* x      = (const float*)d_in[0];
    const float* y      = (const float*)d_in[1];
    const float* z      = (const float*)d_in[2];
    const float* px     = (const float*)d_in[3];
    const float* py     = (const float*)d_in[4];
    const float* pz     = (const float*)d_in[5];
    const float* values = (const float*)d_in[6];
    float* out = (float*)d_out;

    int K = in_sizes[0];
    int threads = 256;
    int blocks = (K + threads - 1) / threads;
    trilerp_kernel<<<blocks, threads>>>(x, y, z, px, py, pz, values, out, K);
}

// round 4
// speedup vs baseline: 1.0642x; 1.0642x over previous
#include <cuda_runtime.h>
#include <cuda_bf16.h>
#include <stdint.h>

#define GRID_N 256

// values gather: L1-cached, non-coherent, L2 evict_last via cache-hint policy
__device__ __forceinline__ float ldg_persist(const float* p, uint64_t policy) {
    float v;
    asm volatile("ld.global.nc.L2::cache_hint.f32 %0, [%1], %2;"
                 : "=f"(v) : "l"(p), "l"(policy));
    return v;
}

// Exact searchsorted(side='left'), analytic seed (axes are linspace) corrected
// against the true axis values held in shared memory.
__device__ __forceinline__ void axis_terms(const float* __restrict__ p, float v,
                                           int& lo, int& hi,
                                           float& dl, float& dr, float& ov) {
    int g = (int)(v * 255.0f) + 1;
    g = min(max(g, 0), GRID_N - 1);
    while (g > 0 && p[g - 1] >= v) g--;
    while (g < GRID_N - 1 && p[g] < v) g++;
    hi = g;
    lo = max(g - 1, 0);
    dl = fmaxf(v - p[lo], 0.0f);
    dr = fmaxf(p[hi] - v, 0.0f);
    if (dl == 0.0f && dr == 0.0f) { dl = 1.0f; dr = 1.0f; }
    ov = dl + dr;
}

__global__ __launch_bounds__(256)
void trilerp_kernel(const float* __restrict__ x,
                    const float* __restrict__ y,
                    const float* __restrict__ z,
                    const float* __restrict__ px,
                    const float* __restrict__ py,
                    const float* __restrict__ pz,
                    const float* __restrict__ values,
                    float* __restrict__ out,
                    int K) {
    __shared__ float spx[GRID_N], spy[GRID_N], spz[GRID_N];
    int t = threadIdx.x;
    if (t < GRID_N) {
        spx[t] = px[t];
        spy[t] = py[t];
        spz[t] = pz[t];
    }
    __syncthreads();

    int i = blockIdx.x * blockDim.x + threadIdx.x;
    if (i >= K) return;

    uint64_t policy;
    asm volatile("createpolicy.fractional.L2::evict_last.b64 %0, 1.0;"
                 : "=l"(policy));

    // streaming loads: evict-first, don't pollute L2
    float vx = __ldcs(x + i);
    float vy = __ldcs(y + i);
    float vz = __ldcs(z + i);

    int xlo, xhi, ylo, yhi, zlo, zhi;
    float dxl, dxr, ovx, dyl, dyr, ovy, dzl, dzr, ovz;
    axis_terms(spx, vx, xlo, xhi, dxl, dxr, ovx);
    axis_terms(spy, vy, ylo, yhi, dyl, dyr, ovy);
    axis_terms(spz, vz, zlo, zhi, dzl, dzr, ovz);

    // values[a][b][c] at ((a*256)+b)*256 + c ; z contiguous
    const float* r00 = values + (((size_t)xlo << 8) + ylo) * GRID_N;
    const float* r01 = values + (((size_t)xlo << 8) + yhi) * GRID_N;
    const float* r10 = values + (((size_t)xhi << 8) + ylo) * GRID_N;
    const float* r11 = values + (((size_t)xhi << 8) + yhi) * GRID_N;

    // 8 independent gathers, L2-persistent
    float v000 = ldg_persist(r00 + zlo, policy);
    float v001 = ldg_persist(r00 + zhi, policy);
    float v010 = ldg_persist(r01 + zlo, policy);
    float v011 = ldg_persist(r01 + zhi, policy);
    float v100 = ldg_persist(r10 + zlo, policy);
    float v101 = ldg_persist(r10 + zhi, policy);
    float v110 = ldg_persist(r11 + zlo, policy);
    float v111 = ldg_persist(r11 + zhi, policy);

    float num =
        v000 * (dxr * dyr * dzr) +
        v001 * (dxr * dyr * dzl) +
        v010 * (dxr * dyl * dzr) +
        v011 * (dxr * dyl * dzl) +
        v100 * (dxl * dyr * dzr) +
        v101 * (dxl * dyr * dzl) +
        v110 * (dxl * dyl * dzr) +
        v111 * (dxl * dyl * dzl);

    __stcs(out + i, num / (ovx * ovy * ovz));
}

extern "C" void kernel_launch(void* const* d_in, const int* in_sizes, int n_in,
                              void* d_out, int out_size) {
    const float* x      = (const float*)d_in[0];
    const float* y      = (const float*)d_in[1];
    const float* z      = (const float*)d_in[2];
    const float* px     = (const float*)d_in[3];
    const float* py     = (const float*)d_in[4];
    const float* pz     = (const float*)d_in[5];
    const float* values = (const float*)d_in[6];
    float* out = (float*)d_out;

    int K = in_sizes[0];
    int threads = 256;
    int blocks = (K + threads - 1) / threads;
    trilerp_kernel<<<blocks, threads>>>(x, y, z, px, py, pz, values, out, K);
}